// round 1
// baseline (speedup 1.0000x reference)
#include <cuda_runtime.h>
#include <math.h>

#define HID 1024
#define G4  4096
#define NB  64
#define SQ  512
#define NA  128

// Scratch (device globals — allocation-free rule)
__device__ float g_gx[(size_t)SQ * NB * G4];   // [S][B][4H]  512 MB
__device__ float g_hs[(size_t)NB * SQ * HID];  // [B][S][H]   128 MB
__device__ float g_h[2][NB * HID];             // double-buffered h
__device__ float g_c[NB * HID];

// ---------------------------------------------------------------------------
// init: zero h0, c0, and the entire output buffer (dummy regions stay zero)
// ---------------------------------------------------------------------------
__global__ void init_zero(float* out, int out_n) {
    int i = blockIdx.x * blockDim.x + threadIdx.x;
    if (i < NB * HID) { g_h[0][i] = 0.f; g_c[i] = 0.f; }
    for (int p = i; p < out_n; p += gridDim.x * blockDim.x) out[p] = 0.f;
}

// ---------------------------------------------------------------------------
// Classic 128x128x8 SGEMM, 256 threads, 8x8 micro-tile.
// GATHER: A row r -> embed[ x[b*SQ + s] ] with r = s*64 + b  (for gx)
// BIAS:   adds bias[n] in epilogue                            (for logits)
// ---------------------------------------------------------------------------
template <bool GATHER, bool BIAS>
__global__ __launch_bounds__(256) void sgemm128(
    const float* __restrict__ A, const float* __restrict__ Bm,
    const float* __restrict__ bias, float* __restrict__ C,
    int N, int K, int ldc,
    const int* __restrict__ tok, const float* __restrict__ table)
{
    __shared__ float As[8][128];
    __shared__ float Bs[8][128];

    const int tid = threadIdx.x;
    const int n0 = blockIdx.x * 128;
    const int m0 = blockIdx.y * 128;

    // A-tile load mapping: 128 rows x 8 k, one float4 per thread
    const int a_row = tid >> 1;
    const int a_col = (tid & 1) << 2;
    const float* arow;
    {
        int r = m0 + a_row;
        if (GATHER) {
            int s = r >> 6;      // r = s*64 + b
            int b = r & 63;
            arow = table + (size_t)tok[b * SQ + s] * HID;
        } else {
            arow = A + (size_t)r * K;
        }
    }
    // B-tile load mapping: 8 rows x 128 n, one float4 per thread
    const int b_row = tid >> 5;
    const int b_col = (tid & 31) << 2;
    const float* bp = Bm + (size_t)b_row * N + n0 + b_col;

    const int ty = tid >> 4;
    const int tx = tid & 15;

    float acc[8][8];
#pragma unroll
    for (int i = 0; i < 8; i++)
#pragma unroll
        for (int j = 0; j < 8; j++) acc[i][j] = 0.f;

    for (int k0 = 0; k0 < K; k0 += 8) {
        float4 av = *(const float4*)(arow + k0 + a_col);
        float4 bv = *(const float4*)(bp + (size_t)k0 * N);
        As[a_col + 0][a_row] = av.x;
        As[a_col + 1][a_row] = av.y;
        As[a_col + 2][a_row] = av.z;
        As[a_col + 3][a_row] = av.w;
        *(float4*)(&Bs[b_row][b_col]) = bv;
        __syncthreads();

#pragma unroll
        for (int k = 0; k < 8; k++) {
            float a[8], b[8];
            *(float4*)(a)     = *(const float4*)(&As[k][ty * 8]);
            *(float4*)(a + 4) = *(const float4*)(&As[k][ty * 8 + 4]);
            *(float4*)(b)     = *(const float4*)(&Bs[k][tx * 8]);
            *(float4*)(b + 4) = *(const float4*)(&Bs[k][tx * 8 + 4]);
#pragma unroll
            for (int i = 0; i < 8; i++)
#pragma unroll
                for (int j = 0; j < 8; j++) acc[i][j] += a[i] * b[j];
        }
        __syncthreads();
    }

#pragma unroll
    for (int i = 0; i < 8; i++) {
        int row = m0 + ty * 8 + i;
        float* cp = C + (size_t)row * ldc + n0 + tx * 8;
#pragma unroll
        for (int j = 0; j < 8; j++) {
            float v = acc[i][j];
            if (BIAS) v += bias[n0 + tx * 8 + j];
            cp[j] = v;
        }
    }
}

// ---------------------------------------------------------------------------
// One LSTM timestep: gates = gx[s] + h_in @ Wh + bh, then cell update.
// Grid: 128 blocks, each owns 8 hidden units j (all 4 gate columns for them)
// across all 64 batch rows. 128 threads, 4x4 micro-tile over [64 x 32].
// h is double-buffered across steps (every block reads ALL of h_in).
// ---------------------------------------------------------------------------
__global__ __launch_bounds__(128) void lstm_step(
    const float* __restrict__ Wh, const float* __restrict__ bh,
    const float* __restrict__ h_in, float* __restrict__ h_out, int s)
{
    __shared__ float As[16][64];   // h tile, transposed: As[k][b]
    __shared__ float Bs[16][32];   // Wh cols: cc -> gate=cc>>3, j=j0+(cc&7)
    __shared__ float Gt[64][32];   // gates staging

    const int tid = threadIdx.x;
    const int j0 = blockIdx.x * 8;

    const int rg = tid >> 3;   // 0..15 : rows b = rg*4 .. rg*4+3
    const int cg = tid & 7;    // 0..7  : cols cc = cg*4 .. cg*4+3

    float acc[4][4];
#pragma unroll
    for (int i = 0; i < 4; i++)
#pragma unroll
        for (int j = 0; j < 4; j++) acc[i][j] = 0.f;

    for (int k0 = 0; k0 < HID; k0 += 16) {
        // As: 64 rows x 16 k = 256 float4, 2 per thread
#pragma unroll
        for (int e = 0; e < 2; e++) {
            int ee = tid + e * 128;
            int b = ee >> 2;
            int c4 = (ee & 3) << 2;
            float4 v = *(const float4*)(h_in + b * HID + k0 + c4);
            As[c4 + 0][b] = v.x;
            As[c4 + 1][b] = v.y;
            As[c4 + 2][b] = v.z;
            As[c4 + 3][b] = v.w;
        }
        // Bs: 512 floats, 4 per thread
#pragma unroll
        for (int e = 0; e < 4; e++) {
            int ee = tid + e * 128;
            int k = ee >> 5;
            int cc = ee & 31;
            Bs[k][cc] = Wh[(size_t)(k0 + k) * G4 + (cc >> 3) * HID + j0 + (cc & 7)];
        }
        __syncthreads();

#pragma unroll
        for (int k = 0; k < 16; k++) {
            float a[4], b[4];
            *(float4*)a = *(const float4*)(&As[k][rg * 4]);
            *(float4*)b = *(const float4*)(&Bs[k][cg * 4]);
#pragma unroll
            for (int i = 0; i < 4; i++)
#pragma unroll
                for (int j = 0; j < 4; j++) acc[i][j] += a[i] * b[j];
        }
        __syncthreads();
    }

    // gates = acc + gx[s] + bh -> stage in smem for regrouping
    const float* gx = g_gx + (size_t)s * NB * G4;
#pragma unroll
    for (int i = 0; i < 4; i++) {
        int b = rg * 4 + i;
#pragma unroll
        for (int j = 0; j < 4; j++) {
            int cc = cg * 4 + j;
            int col = (cc >> 3) * HID + j0 + (cc & 7);
            Gt[b][cc] = acc[i][j] + gx[(size_t)b * G4 + col] + bh[col];
        }
    }
    __syncthreads();

    // elementwise cell update: 512 (b,jj) pairs, 4 per thread
#pragma unroll
    for (int e = 0; e < 4; e++) {
        int p = tid + e * 128;
        int b = p >> 3;
        int jj = p & 7;
        float gi = Gt[b][jj];
        float gf = Gt[b][8 + jj];
        float gg = Gt[b][16 + jj];
        float go = Gt[b][24 + jj];
        gi = 1.f / (1.f + expf(-gi));
        gf = 1.f / (1.f + expf(-gf));
        gg = tanhf(gg);
        go = 1.f / (1.f + expf(-go));
        int j = j0 + jj;
        float cn = gf * g_c[b * HID + j] + gi * gg;
        g_c[b * HID + j] = cn;
        float hn = go * tanhf(cn);
        h_out[b * HID + j] = hn;
        g_hs[((size_t)b * SQ + s) * HID + j] = hn;
    }
}

// ---------------------------------------------------------------------------
extern "C" void kernel_launch(void* const* d_in, const int* in_sizes, int n_in,
                              void* d_out, int out_size)
{
    const float* embed = (const float*)d_in[0];
    const float* Wi    = (const float*)d_in[1];
    const float* Wh    = (const float*)d_in[2];
    const float* bh    = (const float*)d_in[3];
    const float* Wo    = (const float*)d_in[4];
    const float* bo    = (const float*)d_in[5];
    const int*   x     = (const int*)d_in[6];
    float* out = (float*)d_out;

    // Output layout: reference returns (dummy[B,S,1], logits[B,S,A], dummy[B,S,1]).
    // Assume flattened concat in tuple order; handle logits-only too.
    const int TOT = NB * SQ;
    int logits_off = 0;
    if (out_size == TOT * (NA + 2)) logits_off = TOT;   // [dummy | logits | dummy]
    // else: logits at offset 0

    float* gx_ptr = nullptr;
    float* hs_ptr = nullptr;
    float* h_ptr  = nullptr;
    cudaGetSymbolAddress((void**)&gx_ptr, g_gx);
    cudaGetSymbolAddress((void**)&hs_ptr, g_hs);
    cudaGetSymbolAddress((void**)&h_ptr, g_h);

    // 1) zero h0/c0 and the whole output (dummies stay zero)
    init_zero<<<256, 256>>>(out, out_size);

    // 2) gx = gather(embed, x) @ Wi     [32768 x 4096], K=1024
    {
        dim3 grid(G4 / 128, (SQ * NB) / 128);
        sgemm128<true, false><<<grid, 256>>>(
            nullptr, Wi, nullptr, gx_ptr, G4, HID, G4, x, embed);
    }

    // 3) recurrent scan: 512 sequential steps
    for (int s = 0; s < SQ; s++) {
        const float* hin = h_ptr + (s & 1) * NB * HID;
        float* hout = h_ptr + ((s & 1) ^ 1) * NB * HID;
        lstm_step<<<HID / 8, 128>>>(Wh, bh, hin, hout, s);
    }

    // 4) logits = hs @ Wo + bo          [32768 x 128], K=1024
    {
        dim3 grid(NA / 128, (SQ * NB) / 128);
        sgemm128<false, true><<<grid, 256>>>(
            hs_ptr, Wo, bo, out + logits_off, NA, HID, NA, nullptr, nullptr);
    }
}

// round 3
// speedup vs baseline: 2.5013x; 2.5013x over previous
#include <cuda_runtime.h>
#include <cuda_bf16.h>
#include <math.h>
#include <stdint.h>

#define HID 1024
#define G4  4096
#define NB  64
#define SQ  512
#define NA  128
#define MTOT (NB*SQ)

typedef __nv_bfloat16 bf16;

// ---------------- device globals (allocation-free rule) ----------------
__device__ float g_gx[(size_t)SQ*NB*G4];                  // [S][B][4H] fp32
__device__ bf16 g_xe_hi[(size_t)MTOT*HID];
__device__ bf16 g_xe_lo[(size_t)MTOT*HID];
__device__ bf16 g_WiT_hi[(size_t)G4*HID];                 // [n][k]
__device__ bf16 g_WiT_lo[(size_t)G4*HID];
__device__ bf16 g_WhS_hi[(size_t)G4*HID];                 // scan-permuted rows
__device__ bf16 g_WhS_lo[(size_t)G4*HID];
__device__ bf16 g_WoT_hi[(size_t)NA*HID];
__device__ bf16 g_WoT_lo[(size_t)NA*HID];
__device__ bf16 g_hs_hi[(size_t)MTOT*HID];                // [b*SQ+s][j]
__device__ bf16 g_hs_lo[(size_t)MTOT*HID];
__device__ bf16 g_h_hi[2][NB*HID];
__device__ bf16 g_h_lo[2][NB*HID];
__device__ float g_c[NB*HID];
__device__ int g_arrive[128];

// ---------------- helpers ----------------
static __device__ __forceinline__ uint32_t smem_u32(const void* p){
    uint32_t a;
    asm("{ .reg .u64 t; cvta.to.shared.u64 t, %1; cvt.u32.u64 %0, t; }" : "=r"(a) : "l"(p));
    return a;
}
static __device__ __forceinline__ void ldsm4(uint32_t* r, uint32_t a){
    asm volatile("ldmatrix.sync.aligned.m8n8.x4.shared.b16 {%0,%1,%2,%3}, [%4];"
        : "=r"(r[0]),"=r"(r[1]),"=r"(r[2]),"=r"(r[3]) : "r"(a));
}
static __device__ __forceinline__ void mma_bf16(float* d, const uint32_t* a, const uint32_t* b){
    asm volatile("mma.sync.aligned.m16n8k16.row.col.f32.bf16.bf16.f32 "
        "{%0,%1,%2,%3}, {%4,%5,%6,%7}, {%8,%9}, {%0,%1,%2,%3};"
        : "+f"(d[0]),"+f"(d[1]),"+f"(d[2]),"+f"(d[3])
        : "r"(a[0]),"r"(a[1]),"r"(a[2]),"r"(a[3]), "r"(b[0]),"r"(b[1]));
}
static __device__ __forceinline__ void split_bf16(float v, bf16& hi, bf16& lo){
    hi = __float2bfloat16(v);
    lo = __float2bfloat16(v - __bfloat162float(hi));
}

// ---------------- prep kernels ----------------
__global__ void init_zero(float* out, int out_n){
    int i = blockIdx.x * blockDim.x + threadIdx.x;
    int stride = gridDim.x * blockDim.x;
    for (int p = i; p < out_n; p += stride) out[p] = 0.f;
    bf16 z = __float2bfloat16(0.f);
    for (int p = i; p < NB*HID; p += stride){
        g_c[p] = 0.f;
        g_h_hi[0][p] = z; g_h_lo[0][p] = z;
        g_h_hi[1][p] = z; g_h_lo[1][p] = z;
    }
    if (i < 128) g_arrive[i] = 0;
}

// transpose W[K][N] -> T[n][k] split to bf16 hi/lo; PERM reorders Wh rows for the scan
template<bool PERM>
__global__ void transpose_cvt(const float* __restrict__ W,
                              bf16* __restrict__ Thi, bf16* __restrict__ Tlo,
                              int K, int N){
    __shared__ float tile[32][33];
    int k0 = blockIdx.x * 32, n0 = blockIdx.y * 32;
    int tx = threadIdx.x, ty = threadIdx.y;     // 32 x 8
    for (int i = ty; i < 32; i += 8)
        tile[i][tx] = W[(size_t)(k0 + i) * N + n0 + tx];
    __syncthreads();
    for (int i = ty; i < 32; i += 8){
        int n = n0 + i, k = k0 + tx;
        float v = tile[tx][i];
        int r = n;
        if (PERM) r = ((n & 1023) >> 3) * 32 + (n >> 10) * 8 + (n & 7);
        bf16 hi, lo; split_bf16(v, hi, lo);
        Thi[(size_t)r * K + k] = hi;
        Tlo[(size_t)r * K + k] = lo;
    }
}

__global__ void gather_xe(const float* __restrict__ embed, const int* __restrict__ x){
    int r = blockIdx.x;                 // 0..32767, r = s*64 + b
    int s = r >> 6, b = r & 63;
    int tok = x[b * SQ + s];
    const float* src = embed + (size_t)tok * HID;
    for (int k = threadIdx.x; k < HID; k += blockDim.x){
        bf16 hi, lo; split_bf16(src[k], hi, lo);
        g_xe_hi[(size_t)r * HID + k] = hi;
        g_xe_lo[(size_t)r * HID + k] = lo;
    }
}

// ---------------- bf16x3 warp-MMA GEMM ----------------
// C[M,N] tiles 128x64, K=1024. A[m][k] hi/lo, B[n][k] hi/lo -> C fp32 (+bias)
// 8 warps as 4x2; warp tile 32x32. Smem rows padded to 144B (conflict-free ldmatrix).
#define GA_H 0
#define GA_L 18432
#define GB_H 36864
#define GB_L 46080
#define GSM_TOT 55296

__global__ __launch_bounds__(256) void gemm_mma(
    const bf16* __restrict__ Ahi, const bf16* __restrict__ Alo,
    const bf16* __restrict__ Bhi, const bf16* __restrict__ Blo,
    const float* __restrict__ bias, float* __restrict__ C, int ldc)
{
    extern __shared__ char sm[];
    const int tid = threadIdx.x, wid = tid >> 5, l = tid & 31;
    const int n0 = blockIdx.x * 64, m0 = blockIdx.y * 128;
    const int wm0 = (wid & 3) * 32, wn0 = (wid >> 2) * 32;

    uint32_t sbase = smem_u32(sm);
    uint32_t aAh = sbase + GA_H + (uint32_t)(wm0 + (l & 15)) * 144 + (l >> 4) * 16;
    uint32_t aAl = aAh + (GA_L - GA_H);
    const int grp = l >> 3;
    const int n_off = (grp >> 1) * 8 + (l & 7);
    const int kblk = grp & 1;
    uint32_t aBh = sbase + GB_H + (uint32_t)(wn0 + n_off) * 144 + kblk * 16;
    uint32_t aBl = aBh + (GB_L - GB_H);

    float d[2][4][4];
#pragma unroll
    for (int m = 0; m < 2; m++)
#pragma unroll
        for (int q = 0; q < 4; q++)
#pragma unroll
            for (int e = 0; e < 4; e++) d[m][q][e] = 0.f;

    for (int c = 0; c < 16; c++){
        const int k0 = c * 64;
#pragma unroll
        for (int j = 0; j < 4; j++){
            int u = tid + j * 256;
            int row = u >> 3, q = u & 7;
            *(uint4*)(sm + GA_H + row*144 + q*16) = *((const uint4*)(Ahi + (size_t)(m0+row)*HID + k0) + q);
            *(uint4*)(sm + GA_L + row*144 + q*16) = *((const uint4*)(Alo + (size_t)(m0+row)*HID + k0) + q);
        }
#pragma unroll
        for (int j = 0; j < 2; j++){
            int u = tid + j * 256;
            int row = u >> 3, q = u & 7;
            *(uint4*)(sm + GB_H + row*144 + q*16) = *((const uint4*)(Bhi + (size_t)(n0+row)*HID + k0) + q);
            *(uint4*)(sm + GB_L + row*144 + q*16) = *((const uint4*)(Blo + (size_t)(n0+row)*HID + k0) + q);
        }
        __syncthreads();
#pragma unroll
        for (int ks = 0; ks < 4; ks++){
            uint32_t ah[2][4], al[2][4];
            ldsm4(ah[0], aAh + ks*32);
            ldsm4(ah[1], aAh + 16*144 + ks*32);
            ldsm4(al[0], aAl + ks*32);
            ldsm4(al[1], aAl + 16*144 + ks*32);
#pragma unroll
            for (int g = 0; g < 2; g++){
                uint32_t bh4[4], bl4[4];
                ldsm4(bh4, aBh + g*2304 + ks*32);
                ldsm4(bl4, aBl + g*2304 + ks*32);
#pragma unroll
                for (int m = 0; m < 2; m++)
#pragma unroll
                    for (int nn = 0; nn < 2; nn++){
                        float* dd = d[m][g*2+nn];
                        mma_bf16(dd, ah[m], bh4 + nn*2);
                        mma_bf16(dd, ah[m], bl4 + nn*2);
                        mma_bf16(dd, al[m], bh4 + nn*2);
                    }
            }
        }
        __syncthreads();
    }

#pragma unroll
    for (int m = 0; m < 2; m++)
#pragma unroll
        for (int q = 0; q < 4; q++){
            int row0 = m0 + wm0 + m*16 + (l >> 2);
            int col  = n0 + wn0 + q*8 + (l & 3)*2;
            float2 v0 = make_float2(d[m][q][0], d[m][q][1]);
            float2 v1 = make_float2(d[m][q][2], d[m][q][3]);
            if (bias){
                float b0 = bias[col], b1 = bias[col+1];
                v0.x += b0; v0.y += b1; v1.x += b0; v1.y += b1;
            }
            *(float2*)(C + (size_t)row0*ldc + col) = v0;
            *(float2*)(C + (size_t)(row0+8)*ldc + col) = v1;
        }
}

// ---------------- persistent LSTM scan ----------------
// 128 CTAs; CTA owns 8 hidden units = 32 gate cols (rows of WhS). Wh slice resident
// in smem for all 512 steps. Per step: gates = h @ WhS^T (bf16x3), fused cell update,
// then flag-array global barrier.
#define S_WH_H 0
#define S_WH_L 66048
#define S_A_H  132096
#define S_A_L  149504
#define S_GT   166912
#define S_TOT  175104

__global__ __launch_bounds__(256) void lstm_scan(const float* __restrict__ bh){
    extern __shared__ char sm[];
    const int tid = threadIdx.x, wid = tid >> 5, l = tid & 31;
    const int cta = blockIdx.x;

    // resident Wh slice: rows cta*32 .. cta*32+31, stride 2064B
    const bf16* WBhi = g_WhS_hi + (size_t)cta * 32 * HID;
    const bf16* WBlo = g_WhS_lo + (size_t)cta * 32 * HID;
#pragma unroll
    for (int j = 0; j < 16; j++){
        int u = tid + j * 256;
        int row = u >> 7, q = u & 127;
        *(uint4*)(sm + S_WH_H + row*2064 + q*16) = *((const uint4*)(WBhi + (size_t)row*HID) + q);
        *(uint4*)(sm + S_WH_L + row*2064 + q*16) = *((const uint4*)(WBlo + (size_t)row*HID) + q);
    }

    const int wm0 = (wid & 3) * 16, wn0 = (wid >> 2) * 16;
    uint32_t sbase = smem_u32(sm);
    uint32_t aAh = sbase + S_A_H + (uint32_t)(wm0 + (l & 15)) * 272 + (l >> 4) * 16;
    uint32_t aAl = aAh + (S_A_L - S_A_H);
    const int grp = l >> 3;
    const int n_off = (grp >> 1) * 8 + (l & 7);
    const int kblk = grp & 1;
    uint32_t aBh = sbase + S_WH_H + (uint32_t)(wn0 + n_off) * 2064 + kblk * 16;
    uint32_t aBl = aBh + (S_WH_L - S_WH_H);
    float* Gt = (float*)(sm + S_GT);
    __syncthreads();

    for (int s = 0; s < SQ; s++){
        const int sel = s & 1;
        const bf16* hh = g_h_hi[sel];
        const bf16* hl = g_h_lo[sel];
        bf16* nhh = g_h_hi[sel ^ 1];
        bf16* nhl = g_h_lo[sel ^ 1];

        float d[2][4];
#pragma unroll
        for (int nn = 0; nn < 2; nn++)
#pragma unroll
            for (int e = 0; e < 4; e++) d[nn][e] = 0.f;

        for (int c = 0; c < 8; c++){
            const int k0 = c * 128;
#pragma unroll
            for (int j = 0; j < 4; j++){
                int u = tid + j * 256;
                int row = u >> 4, q = u & 15;
                // h written by OTHER SMs in this same launch -> must bypass L1
                *(uint4*)(sm + S_A_H + row*272 + q*16) = __ldcg((const uint4*)(hh + (size_t)row*HID + k0) + q);
                *(uint4*)(sm + S_A_L + row*272 + q*16) = __ldcg((const uint4*)(hl + (size_t)row*HID + k0) + q);
            }
            __syncthreads();
#pragma unroll
            for (int ks = 0; ks < 8; ks++){
                uint32_t ah[4], al[4], bh4[4], bl4[4];
                ldsm4(ah, aAh + ks*32);
                ldsm4(al, aAl + ks*32);
                ldsm4(bh4, aBh + c*256 + ks*32);
                ldsm4(bl4, aBl + c*256 + ks*32);
#pragma unroll
                for (int nn = 0; nn < 2; nn++){
                    mma_bf16(d[nn], ah, bh4 + nn*2);
                    mma_bf16(d[nn], ah, bl4 + nn*2);
                    mma_bf16(d[nn], al, bh4 + nn*2);
                }
            }
            __syncthreads();
        }

        // stage gate values: Gt[b][cc], cc = gate*8 + jj
#pragma unroll
        for (int nn = 0; nn < 2; nn++){
            int r = wm0 + (l >> 2);
            int cc = wn0 + nn*8 + (l & 3)*2;
            Gt[r*32 + cc]     = d[nn][0];
            Gt[r*32 + cc + 1] = d[nn][1];
            Gt[(r+8)*32 + cc]     = d[nn][2];
            Gt[(r+8)*32 + cc + 1] = d[nn][3];
        }
        __syncthreads();

        // fused cell update: 512 (b,jj) pairs, 2 per thread
#pragma unroll
        for (int e = 0; e < 2; e++){
            int p = tid + e * 256;
            int b = p >> 3, jj = p & 7;
            int jb = cta * 8 + jj;
            const float* gxr = g_gx + ((size_t)s * NB + b) * G4;
            float gi = Gt[b*32 + jj]      + gxr[jb]          + bh[jb];
            float gf = Gt[b*32 + 8 + jj]  + gxr[HID + jb]    + bh[HID + jb];
            float gg = Gt[b*32 + 16 + jj] + gxr[2*HID + jb]  + bh[2*HID + jb];
            float go = Gt[b*32 + 24 + jj] + gxr[3*HID + jb]  + bh[3*HID + jb];
            gi = 1.f / (1.f + expf(-gi));
            gf = 1.f / (1.f + expf(-gf));
            gg = tanhf(gg);
            go = 1.f / (1.f + expf(-go));
            float cn = gf * g_c[b*HID + jb] + gi * gg;
            g_c[b*HID + jb] = cn;
            float hn = go * tanhf(cn);
            bf16 hi16, lo16; split_bf16(hn, hi16, lo16);
            nhh[b*HID + jb] = hi16;
            nhl[b*HID + jb] = lo16;
            size_t ho = ((size_t)b * SQ + s) * HID + jb;
            g_hs_hi[ho] = hi16;
            g_hs_lo[ho] = lo16;
        }
        __syncthreads();

        // global barrier: per-CTA release-store, 128-slot acquire-poll
        if (tid == 0){
            __threadfence();
            asm volatile("st.release.gpu.global.b32 [%0], %1;"
                         :: "l"(g_arrive + cta), "r"(s + 1) : "memory");
        }
        for (;;){
            int v = s + 1;
            if (tid < 128)
                asm volatile("ld.acquire.gpu.global.b32 %0, [%1];"
                             : "=r"(v) : "l"(g_arrive + tid) : "memory");
            if (__syncthreads_and(v >= s + 1)) break;
        }
    }
}

// ---------------------------------------------------------------------------
extern "C" void kernel_launch(void* const* d_in, const int* in_sizes, int n_in,
                              void* d_out, int out_size){
    const float* embed = (const float*)d_in[0];
    const float* Wi    = (const float*)d_in[1];
    const float* Wh    = (const float*)d_in[2];
    const float* bh    = (const float*)d_in[3];
    const float* Wo    = (const float*)d_in[4];
    const float* bo    = (const float*)d_in[5];
    const int*   x     = (const int*)d_in[6];
    float* out = (float*)d_out;

    const int TOT = NB * SQ;
    int logits_off = 0;
    if (out_size == TOT * (NA + 2)) logits_off = TOT;   // [dummy | logits | dummy]

    static int attr_done = 0;
    cudaFuncSetAttribute(gemm_mma,  cudaFuncAttributeMaxDynamicSharedMemorySize, GSM_TOT);
    cudaFuncSetAttribute(lstm_scan, cudaFuncAttributeMaxDynamicSharedMemorySize, S_TOT);
    (void)attr_done;

    float *gx_p;
    cudaGetSymbolAddress((void**)&gx_p, g_gx);
    bf16 *xeh, *xel, *wih, *wil, *woh, *wol, *hsh, *hsl, *whh, *whl;
    cudaGetSymbolAddress((void**)&xeh, g_xe_hi);
    cudaGetSymbolAddress((void**)&xel, g_xe_lo);
    cudaGetSymbolAddress((void**)&wih, g_WiT_hi);
    cudaGetSymbolAddress((void**)&wil, g_WiT_lo);
    cudaGetSymbolAddress((void**)&woh, g_WoT_hi);
    cudaGetSymbolAddress((void**)&wol, g_WoT_lo);
    cudaGetSymbolAddress((void**)&hsh, g_hs_hi);
    cudaGetSymbolAddress((void**)&hsl, g_hs_lo);
    cudaGetSymbolAddress((void**)&whh, g_WhS_hi);
    cudaGetSymbolAddress((void**)&whl, g_WhS_lo);

    // 1) zero out + h0/c0 + barrier slots
    init_zero<<<512, 256>>>(out, out_size);

    // 2) weight transpose+split, embedding gather+split
    transpose_cvt<false><<<dim3(32, 128), dim3(32, 8)>>>(Wi, wih, wil, HID, G4);
    transpose_cvt<true ><<<dim3(32, 128), dim3(32, 8)>>>(Wh, whh, whl, HID, G4);
    transpose_cvt<false><<<dim3(32, 4),   dim3(32, 8)>>>(Wo, woh, wol, HID, NA);
    gather_xe<<<MTOT, 128>>>(embed, x);

    // 3) gx = xe @ WiT^T  [32768 x 4096]
    gemm_mma<<<dim3(G4/64, MTOT/128), 256, GSM_TOT>>>(xeh, xel, wih, wil, nullptr, gx_p, G4);

    // 4) persistent recurrent scan
    lstm_scan<<<128, 256, S_TOT>>>(bh);

    // 5) logits = hs @ WoT^T + bo  [32768 x 128]
    gemm_mma<<<dim3(NA/64, MTOT/128), 256, GSM_TOT>>>(hsh, hsl, woh, wol, bo, out + logits_off, NA);
}

// round 4
// speedup vs baseline: 4.0796x; 1.6310x over previous
#include <cuda_runtime.h>
#include <cuda_fp16.h>
#include <math.h>
#include <stdint.h>

#define HID 1024
#define G4  4096
#define NB  64
#define SQ  512
#define NA  128
#define MTOT (NB*SQ)

typedef __half half_t;

// ---------------- device globals (allocation-free rule) ----------------
__device__ float g_gx[(size_t)SQ*NB*G4];                  // [S][B][4H] fp32
__device__ half_t g_xe[(size_t)MTOT*HID];                 // activations: single fp16
__device__ half_t g_WiT_hi[(size_t)G4*HID];               // weights: fp16 hi/lo
__device__ half_t g_WiT_lo[(size_t)G4*HID];
__device__ half_t g_WhS_hi[(size_t)G4*HID];               // scan-permuted rows
__device__ half_t g_WhS_lo[(size_t)G4*HID];
__device__ half_t g_WoT_hi[(size_t)NA*HID];
__device__ half_t g_WoT_lo[(size_t)NA*HID];
__device__ half_t g_hs[(size_t)MTOT*HID];                 // [b*SQ+s][j]
__device__ half_t g_h[2][NB*HID];
__device__ float g_c[NB*HID];
__device__ unsigned int g_cnt;

// ---------------- helpers ----------------
static __device__ __forceinline__ uint32_t smem_u32(const void* p){
    uint32_t a;
    asm("{ .reg .u64 t; cvta.to.shared.u64 t, %1; cvt.u32.u64 %0, t; }" : "=r"(a) : "l"(p));
    return a;
}
static __device__ __forceinline__ void ldsm4(uint32_t* r, uint32_t a){
    asm volatile("ldmatrix.sync.aligned.m8n8.x4.shared.b16 {%0,%1,%2,%3}, [%4];"
        : "=r"(r[0]),"=r"(r[1]),"=r"(r[2]),"=r"(r[3]) : "r"(a));
}
static __device__ __forceinline__ void mma_f16(float* d, const uint32_t* a, const uint32_t* b){
    asm volatile("mma.sync.aligned.m16n8k16.row.col.f32.f16.f16.f32 "
        "{%0,%1,%2,%3}, {%4,%5,%6,%7}, {%8,%9}, {%0,%1,%2,%3};"
        : "+f"(d[0]),"+f"(d[1]),"+f"(d[2]),"+f"(d[3])
        : "r"(a[0]),"r"(a[1]),"r"(a[2]),"r"(a[3]), "r"(b[0]),"r"(b[1]));
}
static __device__ __forceinline__ void cp16(uint32_t dst, const void* src){
    asm volatile("cp.async.cg.shared.global [%0], [%1], 16;" :: "r"(dst), "l"(src));
}
#define CP_COMMIT() asm volatile("cp.async.commit_group;" ::: "memory")
#define CP_WAIT(n)  asm volatile("cp.async.wait_group %0;" :: "n"(n) : "memory")

static __device__ __forceinline__ void split_f16(float v, half_t& hi, half_t& lo){
    hi = __float2half_rn(v);
    lo = __float2half_rn(v - __half2float(hi));
}

// ---------------- prep kernels ----------------
__global__ void init_zero(float* out, int out_n){
    int i = blockIdx.x * blockDim.x + threadIdx.x;
    int stride = gridDim.x * blockDim.x;
    for (int p = i; p < out_n; p += stride) out[p] = 0.f;
    half_t z = __float2half(0.f);
    for (int p = i; p < NB*HID; p += stride){
        g_c[p] = 0.f;
        g_h[0][p] = z; g_h[1][p] = z;
    }
    if (i == 0) g_cnt = 0u;
}

// transpose W[K][N] -> T[n][k] split to fp16 hi/lo; PERM reorders Wh rows for the scan
template<bool PERM>
__global__ void transpose_cvt(const float* __restrict__ W,
                              half_t* __restrict__ Thi, half_t* __restrict__ Tlo,
                              int K, int N){
    __shared__ float tile[32][33];
    int k0 = blockIdx.x * 32, n0 = blockIdx.y * 32;
    int tx = threadIdx.x, ty = threadIdx.y;     // 32 x 8
    for (int i = ty; i < 32; i += 8)
        tile[i][tx] = W[(size_t)(k0 + i) * N + n0 + tx];
    __syncthreads();
    for (int i = ty; i < 32; i += 8){
        int n = n0 + i, k = k0 + tx;
        float v = tile[tx][i];
        int r = n;
        if (PERM) r = ((n & 1023) >> 3) * 32 + (n >> 10) * 8 + (n & 7);
        half_t hi, lo; split_f16(v, hi, lo);
        Thi[(size_t)r * K + k] = hi;
        Tlo[(size_t)r * K + k] = lo;
    }
}

__global__ void gather_xe(const float* __restrict__ embed, const int* __restrict__ x){
    int r = blockIdx.x;                 // 0..32767, r = s*64 + b
    int s = r >> 6, b = r & 63;
    int tok = x[b * SQ + s];
    const float* src = embed + (size_t)tok * HID;
    for (int k = threadIdx.x; k < HID; k += blockDim.x)
        g_xe[(size_t)r * HID + k] = __float2half_rn(src[k]);
}

// ---------------- fp16x2 warp-MMA GEMM ----------------
// C[M,N] tiles 128x64, K=1024. A[m][k] fp16, B[n][k] fp16 hi/lo -> C fp32 (+bias)
// 8 warps 4x2, warp tile 32x32. Rows padded to 144B. cp.async double-buffered.
#define GBUF   36864            // per buffer: A 18432 | Bh 9216 | Bl 9216
#define G_AO   0
#define G_BHO  18432
#define G_BLO  27648
#define GSM_TOT (2*GBUF)

__global__ __launch_bounds__(256) void gemm_mma(
    const half_t* __restrict__ A,
    const half_t* __restrict__ Bhi, const half_t* __restrict__ Blo,
    const float* __restrict__ bias, float* __restrict__ C, int ldc)
{
    extern __shared__ char sm[];
    const int tid = threadIdx.x, wid = tid >> 5, l = tid & 31;
    const int n0 = blockIdx.x * 64, m0 = blockIdx.y * 128;
    const int wm0 = (wid & 3) * 32, wn0 = (wid >> 2) * 32;

    uint32_t sbase = smem_u32(sm);

    // load mappings
    const int a_row = tid >> 1, a_q = tid & 1;             // 128 rows x 2 (x4 iters covers 8 q)
    const int b_row = tid >> 2, b_q = tid & 3;             // 64 rows x 4 (x2 iters covers 8 q)

    // fragment addrs (per buffer add buf*GBUF)
    uint32_t aA = sbase + G_AO + (uint32_t)(wm0 + (l & 15)) * 144 + (l >> 4) * 16;
    const int grp = l >> 3;
    const int n_off = (grp >> 1) * 8 + (l & 7);
    const int kblk = grp & 1;
    uint32_t aBh = sbase + G_BHO + (uint32_t)(wn0 + n_off) * 144 + kblk * 16;
    uint32_t aBl = sbase + G_BLO + (uint32_t)(wn0 + n_off) * 144 + kblk * 16;

    float d[2][4][4];
#pragma unroll
    for (int m = 0; m < 2; m++)
#pragma unroll
        for (int q = 0; q < 4; q++)
#pragma unroll
            for (int e = 0; e < 4; e++) d[m][q][e] = 0.f;

    // chunk issue: k-chunk of 64 into buffer buf
    auto issue = [&](int c, int buf){
        const int k0 = c * 64;
        uint32_t bb = sbase + buf * GBUF;
#pragma unroll
        for (int j = 0; j < 4; j++){
            int q = a_q + j * 2;
            cp16(bb + G_AO + a_row*144 + q*16, A + (size_t)(m0 + a_row)*HID + k0 + q*8);
        }
#pragma unroll
        for (int j = 0; j < 2; j++){
            int q = b_q + j * 4;
            cp16(bb + G_BHO + b_row*144 + q*16, Bhi + (size_t)(n0 + b_row)*HID + k0 + q*8);
            cp16(bb + G_BLO + b_row*144 + q*16, Blo + (size_t)(n0 + b_row)*HID + k0 + q*8);
        }
    };

    issue(0, 0); CP_COMMIT();

    for (int c = 0; c < 16; c++){
        if (c < 15){ issue(c + 1, (c + 1) & 1); CP_COMMIT(); CP_WAIT(1); }
        else CP_WAIT(0);
        __syncthreads();
        const uint32_t bo = (uint32_t)(c & 1) * GBUF;
#pragma unroll
        for (int ks = 0; ks < 4; ks++){
            uint32_t ah[2][4];
            ldsm4(ah[0], aA + bo + ks*32);
            ldsm4(ah[1], aA + bo + 16*144 + ks*32);
#pragma unroll
            for (int g = 0; g < 2; g++){
                uint32_t bh4[4], bl4[4];
                ldsm4(bh4, aBh + bo + g*2304 + ks*32);
                ldsm4(bl4, aBl + bo + g*2304 + ks*32);
#pragma unroll
                for (int m = 0; m < 2; m++)
#pragma unroll
                    for (int nn = 0; nn < 2; nn++){
                        float* dd = d[m][g*2+nn];
                        mma_f16(dd, ah[m], bh4 + nn*2);
                        mma_f16(dd, ah[m], bl4 + nn*2);
                    }
            }
        }
        __syncthreads();
    }

#pragma unroll
    for (int m = 0; m < 2; m++)
#pragma unroll
        for (int q = 0; q < 4; q++){
            int row0 = m0 + wm0 + m*16 + (l >> 2);
            int col  = n0 + wn0 + q*8 + (l & 3)*2;
            float2 v0 = make_float2(d[m][q][0], d[m][q][1]);
            float2 v1 = make_float2(d[m][q][2], d[m][q][3]);
            if (bias){
                float b0 = bias[col], b1 = bias[col+1];
                v0.x += b0; v0.y += b1; v1.x += b0; v1.y += b1;
            }
            *(float2*)(C + (size_t)row0*ldc + col) = v0;
            *(float2*)(C + (size_t)(row0+8)*ldc + col) = v1;
        }
}

// ---------------- persistent LSTM scan ----------------
// 128 CTAs; CTA owns 8 hidden units = 32 gate cols. Wh slice (hi/lo fp16) resident
// in smem for all 512 steps. h single fp16, cp.async double-buffered.
#define S_WH_H 0
#define S_WH_L 66048
#define S_A0   132096
#define S_A1   149504
#define S_GT   166912
#define S_TOT  175104

__global__ __launch_bounds__(256) void lstm_scan(const float* __restrict__ bh){
    extern __shared__ char sm[];
    const int tid = threadIdx.x, wid = tid >> 5, l = tid & 31;
    const int cta = blockIdx.x;

    // resident Wh slice: rows cta*32 .. cta*32+31, stride 2064B
    const half_t* WBhi = g_WhS_hi + (size_t)cta * 32 * HID;
    const half_t* WBlo = g_WhS_lo + (size_t)cta * 32 * HID;
#pragma unroll
    for (int j = 0; j < 16; j++){
        int u = tid + j * 256;
        int row = u >> 7, q = u & 127;
        *(uint4*)(sm + S_WH_H + row*2064 + q*16) = *((const uint4*)(WBhi + (size_t)row*HID) + q);
        *(uint4*)(sm + S_WH_L + row*2064 + q*16) = *((const uint4*)(WBlo + (size_t)row*HID) + q);
    }

    const int wm0 = (wid & 3) * 16, wn0 = (wid >> 2) * 16;
    uint32_t sbase = smem_u32(sm);
    uint32_t aA0 = sbase + S_A0 + (uint32_t)(wm0 + (l & 15)) * 272 + (l >> 4) * 16;
    uint32_t aA1 = sbase + S_A1 + (uint32_t)(wm0 + (l & 15)) * 272 + (l >> 4) * 16;
    const int grp = l >> 3;
    const int n_off = (grp >> 1) * 8 + (l & 7);
    const int kblk = grp & 1;
    uint32_t aBh = sbase + S_WH_H + (uint32_t)(wn0 + n_off) * 2064 + kblk * 16;
    uint32_t aBl = sbase + S_WH_L + (uint32_t)(wn0 + n_off) * 2064 + kblk * 16;
    float* Gt = (float*)(sm + S_GT);

    const int a_row = tid >> 2, a_q = tid & 3;   // 64 rows x 4 (x4 iters covers 16 q)
    __syncthreads();

    for (int s = 0; s < SQ; s++){
        const int sel = s & 1;
        const half_t* hh = g_h[sel];
        half_t* nhh = g_h[sel ^ 1];

        auto issueA = [&](int c, int buf){
            const int k0 = c * 128;
            uint32_t bb = sbase + (buf ? S_A1 : S_A0);
#pragma unroll
            for (int j = 0; j < 4; j++){
                int q = a_q + j * 4;
                cp16(bb + a_row*272 + q*16, hh + (size_t)a_row*HID + k0 + q*8);
            }
        };

        float d[2][4];
#pragma unroll
        for (int nn = 0; nn < 2; nn++)
#pragma unroll
            for (int e = 0; e < 4; e++) d[nn][e] = 0.f;

        issueA(0, 0); CP_COMMIT();
        for (int c = 0; c < 8; c++){
            if (c < 7){ issueA(c + 1, (c + 1) & 1); CP_COMMIT(); CP_WAIT(1); }
            else CP_WAIT(0);
            __syncthreads();
            uint32_t aA = (c & 1) ? aA1 : aA0;
#pragma unroll
            for (int ks = 0; ks < 8; ks++){
                uint32_t ah[4], bh4[4], bl4[4];
                ldsm4(ah, aA + ks*32);
                ldsm4(bh4, aBh + c*256 + ks*32);
                ldsm4(bl4, aBl + c*256 + ks*32);
#pragma unroll
                for (int nn = 0; nn < 2; nn++){
                    mma_f16(d[nn], ah, bh4 + nn*2);
                    mma_f16(d[nn], ah, bl4 + nn*2);
                }
            }
            __syncthreads();
        }

        // stage gate values: Gt[b][cc], cc = gate*8 + jj
#pragma unroll
        for (int nn = 0; nn < 2; nn++){
            int r = wm0 + (l >> 2);
            int cc = wn0 + nn*8 + (l & 3)*2;
            Gt[r*32 + cc]     = d[nn][0];
            Gt[r*32 + cc + 1] = d[nn][1];
            Gt[(r+8)*32 + cc]     = d[nn][2];
            Gt[(r+8)*32 + cc + 1] = d[nn][3];
        }
        __syncthreads();

        // fused cell update: 512 (b,jj) pairs, 2 per thread
#pragma unroll
        for (int e = 0; e < 2; e++){
            int p = tid + e * 256;
            int b = p >> 3, jj = p & 7;
            int jb = cta * 8 + jj;
            const float* gxr = g_gx + ((size_t)s * NB + b) * G4;
            float gi = Gt[b*32 + jj]      + gxr[jb]          + bh[jb];
            float gf = Gt[b*32 + 8 + jj]  + gxr[HID + jb]    + bh[HID + jb];
            float gg = Gt[b*32 + 16 + jj] + gxr[2*HID + jb]  + bh[2*HID + jb];
            float go = Gt[b*32 + 24 + jj] + gxr[3*HID + jb]  + bh[3*HID + jb];
            gi = 1.f / (1.f + expf(-gi));
            gf = 1.f / (1.f + expf(-gf));
            gg = tanhf(gg);
            go = 1.f / (1.f + expf(-go));
            float cn = gf * g_c[b*HID + jb] + gi * gg;
            g_c[b*HID + jb] = cn;
            float hn = go * tanhf(cn);
            half_t h16 = __float2half_rn(hn);
            nhh[b*HID + jb] = h16;
            g_hs[((size_t)b * SQ + s) * HID + jb] = h16;
        }
        __syncthreads();

        // global barrier: release-atomic counter + single acquire-poller
        if (tid == 0){
            unsigned int dummy;
            asm volatile("atom.add.release.gpu.global.u32 %0, [%1], 1;"
                         : "=r"(dummy) : "l"(&g_cnt) : "memory");
            unsigned int target = 128u * (unsigned int)(s + 1);
            unsigned int v;
            do {
                asm volatile("ld.acquire.gpu.global.u32 %0, [%1];"
                             : "=r"(v) : "l"(&g_cnt) : "memory");
            } while (v < target);
        }
        __syncthreads();
    }
}

// ---------------------------------------------------------------------------
extern "C" void kernel_launch(void* const* d_in, const int* in_sizes, int n_in,
                              void* d_out, int out_size){
    const float* embed = (const float*)d_in[0];
    const float* Wi    = (const float*)d_in[1];
    const float* Wh    = (const float*)d_in[2];
    const float* bh    = (const float*)d_in[3];
    const float* Wo    = (const float*)d_in[4];
    const float* bo    = (const float*)d_in[5];
    const int*   x     = (const int*)d_in[6];
    float* out = (float*)d_out;

    const int TOT = NB * SQ;
    int logits_off = 0;
    if (out_size == TOT * (NA + 2)) logits_off = TOT;   // [dummy | logits | dummy]

    cudaFuncSetAttribute(gemm_mma,  cudaFuncAttributeMaxDynamicSharedMemorySize, GSM_TOT);
    cudaFuncSetAttribute(lstm_scan, cudaFuncAttributeMaxDynamicSharedMemorySize, S_TOT);

    float *gx_p;
    cudaGetSymbolAddress((void**)&gx_p, g_gx);
    half_t *xe, *wih, *wil, *woh, *wol, *hs, *whh, *whl;
    cudaGetSymbolAddress((void**)&xe,  g_xe);
    cudaGetSymbolAddress((void**)&wih, g_WiT_hi);
    cudaGetSymbolAddress((void**)&wil, g_WiT_lo);
    cudaGetSymbolAddress((void**)&woh, g_WoT_hi);
    cudaGetSymbolAddress((void**)&wol, g_WoT_lo);
    cudaGetSymbolAddress((void**)&hs,  g_hs);
    cudaGetSymbolAddress((void**)&whh, g_WhS_hi);
    cudaGetSymbolAddress((void**)&whl, g_WhS_lo);

    // 1) zero out + h0/c0 + barrier counter
    init_zero<<<512, 256>>>(out, out_size);

    // 2) weight transpose+split, embedding gather
    transpose_cvt<false><<<dim3(32, 128), dim3(32, 8)>>>(Wi, wih, wil, HID, G4);
    transpose_cvt<true ><<<dim3(32, 128), dim3(32, 8)>>>(Wh, whh, whl, HID, G4);
    transpose_cvt<false><<<dim3(32, 4),   dim3(32, 8)>>>(Wo, woh, wol, HID, NA);
    gather_xe<<<MTOT, 128>>>(embed, x);

    // 3) gx = xe @ WiT^T  [32768 x 4096]
    gemm_mma<<<dim3(G4/64, MTOT/128), 256, GSM_TOT>>>(xe, wih, wil, nullptr, gx_p, G4);

    // 4) persistent recurrent scan
    lstm_scan<<<128, 256, S_TOT>>>(bh);

    // 5) logits = hs @ WoT^T + bo  [32768 x 128]
    gemm_mma<<<dim3(NA/64, MTOT/128), 256, GSM_TOT>>>(hs, woh, wol, bo, out + logits_off, NA);
}

// round 6
// speedup vs baseline: 6.1160x; 1.4992x over previous
#include <cuda_runtime.h>
#include <cuda_fp16.h>
#include <math.h>
#include <stdint.h>

#define HID 1024
#define G4  4096
#define NB  64
#define SQ  512
#define NA  128
#define MTOT (NB*SQ)

typedef __half half_t;

// ---------------- device globals (allocation-free rule) ----------------
__device__ float g_gx[(size_t)SQ*NB*G4];                  // [S][B][4H] fp32
__device__ half_t g_xe[(size_t)MTOT*HID];                 // activations: single fp16
__device__ half_t g_WiT_hi[(size_t)G4*HID];               // weights: fp16 hi/lo
__device__ half_t g_WiT_lo[(size_t)G4*HID];
__device__ half_t g_WhS_hi[(size_t)G4*HID];               // scan-permuted rows (hi used)
__device__ half_t g_WhS_lo[(size_t)G4*HID];
__device__ half_t g_WoT_hi[(size_t)NA*HID];
__device__ half_t g_WoT_lo[(size_t)NA*HID];
__device__ half_t g_hs[(size_t)MTOT*HID];                 // [b*SQ+s][j]
__device__ half_t g_h[2][NB*HID];
__device__ unsigned int g_cnt2[64];                       // per-group barrier counters

// ---------------- helpers ----------------
static __device__ __forceinline__ uint32_t smem_u32(const void* p){
    uint32_t a;
    asm("{ .reg .u64 t; cvta.to.shared.u64 t, %1; cvt.u32.u64 %0, t; }" : "=r"(a) : "l"(p));
    return a;
}
static __device__ __forceinline__ void ldsm4(uint32_t* r, uint32_t a){
    asm volatile("ldmatrix.sync.aligned.m8n8.x4.shared.b16 {%0,%1,%2,%3}, [%4];"
        : "=r"(r[0]),"=r"(r[1]),"=r"(r[2]),"=r"(r[3]) : "r"(a));
}
static __device__ __forceinline__ void mma_f16(float* d, const uint32_t* a, const uint32_t* b){
    asm volatile("mma.sync.aligned.m16n8k16.row.col.f32.f16.f16.f32 "
        "{%0,%1,%2,%3}, {%4,%5,%6,%7}, {%8,%9}, {%0,%1,%2,%3};"
        : "+f"(d[0]),"+f"(d[1]),"+f"(d[2]),"+f"(d[3])
        : "r"(a[0]),"r"(a[1]),"r"(a[2]),"r"(a[3]), "r"(b[0]),"r"(b[1]));
}
static __device__ __forceinline__ void cp16(uint32_t dst, const void* src){
    asm volatile("cp.async.cg.shared.global [%0], [%1], 16;" :: "r"(dst), "l"(src));
}
#define CP_COMMIT() asm volatile("cp.async.commit_group;" ::: "memory")
#define CP_WAIT(n)  asm volatile("cp.async.wait_group %0;" :: "n"(n) : "memory")

static __device__ __forceinline__ void split_f16(float v, half_t& hi, half_t& lo){
    hi = __float2half_rn(v);
    lo = __float2half_rn(v - __half2float(hi));
}

// ---------------- prep kernels ----------------
__global__ void init_zero(float* out, int out_n){
    int i = blockIdx.x * blockDim.x + threadIdx.x;
    int stride = gridDim.x * blockDim.x;
    for (int p = i; p < out_n; p += stride) out[p] = 0.f;
    half_t z = __float2half(0.f);
    for (int p = i; p < NB*HID; p += stride){
        g_h[0][p] = z; g_h[1][p] = z;
    }
    if (i < 64) g_cnt2[i] = 0u;
}

// transpose W[K][N] -> T[n][k] split to fp16 hi/lo; PERM reorders Wh rows for the scan:
// CTA c owns units j=c*16..+15; slice row cc = gate*16 + (j&15); global row = c*64 + cc
template<bool PERM>
__global__ void transpose_cvt(const float* __restrict__ W,
                              half_t* __restrict__ Thi, half_t* __restrict__ Tlo,
                              int K, int N){
    __shared__ float tile[32][33];
    int k0 = blockIdx.x * 32, n0 = blockIdx.y * 32;
    int tx = threadIdx.x, ty = threadIdx.y;     // 32 x 8
    for (int i = ty; i < 32; i += 8)
        tile[i][tx] = W[(size_t)(k0 + i) * N + n0 + tx];
    __syncthreads();
    for (int i = ty; i < 32; i += 8){
        int n = n0 + i, k = k0 + tx;
        float v = tile[tx][i];
        int r = n;
        if (PERM) r = ((n & 1023) >> 4) * 64 + (n >> 10) * 16 + (n & 15);
        half_t hi, lo; split_f16(v, hi, lo);
        Thi[(size_t)r * K + k] = hi;
        Tlo[(size_t)r * K + k] = lo;
    }
}

__global__ void gather_xe(const float* __restrict__ embed, const int* __restrict__ x){
    int r = blockIdx.x;                 // 0..32767, r = s*64 + b
    int s = r >> 6, b = r & 63;
    int tok = x[b * SQ + s];
    const float* src = embed + (size_t)tok * HID;
    for (int k = threadIdx.x; k < HID; k += blockDim.x)
        g_xe[(size_t)r * HID + k] = __float2half_rn(src[k]);
}

// ---------------- fp16x2 warp-MMA GEMM ----------------
// C[M,N] tiles 128x64, K=1024. A[m][k] fp16, B[n][k] fp16 hi/lo -> C fp32 (+bias)
// 8 warps 4x2, warp tile 32x32. Rows padded to 144B. cp.async double-buffered.
#define GBUF   36864            // per buffer: A 18432 | Bh 9216 | Bl 9216
#define G_AO   0
#define G_BHO  18432
#define G_BLO  27648
#define GSM_TOT (2*GBUF)

__global__ __launch_bounds__(256) void gemm_mma(
    const half_t* __restrict__ A,
    const half_t* __restrict__ Bhi, const half_t* __restrict__ Blo,
    const float* __restrict__ bias, float* __restrict__ C, int ldc)
{
    extern __shared__ char sm[];
    const int tid = threadIdx.x, wid = tid >> 5, l = tid & 31;
    const int n0 = blockIdx.x * 64, m0 = blockIdx.y * 128;
    const int wm0 = (wid & 3) * 32, wn0 = (wid >> 2) * 32;

    uint32_t sbase = smem_u32(sm);

    const int a_row = tid >> 1, a_q = tid & 1;
    const int b_row = tid >> 2, b_q = tid & 3;

    uint32_t aA = sbase + G_AO + (uint32_t)(wm0 + (l & 15)) * 144 + (l >> 4) * 16;
    const int grp = l >> 3;
    const int n_off = (grp >> 1) * 8 + (l & 7);
    const int kblk = grp & 1;
    uint32_t aBh = sbase + G_BHO + (uint32_t)(wn0 + n_off) * 144 + kblk * 16;
    uint32_t aBl = sbase + G_BLO + (uint32_t)(wn0 + n_off) * 144 + kblk * 16;

    float d[2][4][4];
#pragma unroll
    for (int m = 0; m < 2; m++)
#pragma unroll
        for (int q = 0; q < 4; q++)
#pragma unroll
            for (int e = 0; e < 4; e++) d[m][q][e] = 0.f;

    auto issue = [&](int c, int buf){
        const int k0 = c * 64;
        uint32_t bb = sbase + buf * GBUF;
#pragma unroll
        for (int j = 0; j < 4; j++){
            int q = a_q + j * 2;
            cp16(bb + G_AO + a_row*144 + q*16, A + (size_t)(m0 + a_row)*HID + k0 + q*8);
        }
#pragma unroll
        for (int j = 0; j < 2; j++){
            int q = b_q + j * 4;
            cp16(bb + G_BHO + b_row*144 + q*16, Bhi + (size_t)(n0 + b_row)*HID + k0 + q*8);
            cp16(bb + G_BLO + b_row*144 + q*16, Blo + (size_t)(n0 + b_row)*HID + k0 + q*8);
        }
    };

    issue(0, 0); CP_COMMIT();

    for (int c = 0; c < 16; c++){
        if (c < 15){ issue(c + 1, (c + 1) & 1); CP_COMMIT(); CP_WAIT(1); }
        else CP_WAIT(0);
        __syncthreads();
        const uint32_t bo = (uint32_t)(c & 1) * GBUF;
#pragma unroll
        for (int ks = 0; ks < 4; ks++){
            uint32_t ah[2][4];
            ldsm4(ah[0], aA + bo + ks*32);
            ldsm4(ah[1], aA + bo + 16*144 + ks*32);
#pragma unroll
            for (int g = 0; g < 2; g++){
                uint32_t bh4[4], bl4[4];
                ldsm4(bh4, aBh + bo + g*2304 + ks*32);
                ldsm4(bl4, aBl + bo + g*2304 + ks*32);
#pragma unroll
                for (int m = 0; m < 2; m++)
#pragma unroll
                    for (int nn = 0; nn < 2; nn++){
                        float* dd = d[m][g*2+nn];
                        mma_f16(dd, ah[m], bh4 + nn*2);
                        mma_f16(dd, ah[m], bl4 + nn*2);
                    }
            }
        }
        __syncthreads();
    }

#pragma unroll
    for (int m = 0; m < 2; m++)
#pragma unroll
        for (int q = 0; q < 4; q++){
            int row0 = m0 + wm0 + m*16 + (l >> 2);
            int col  = n0 + wn0 + q*8 + (l & 3)*2;
            float2 v0 = make_float2(d[m][q][0], d[m][q][1]);
            float2 v1 = make_float2(d[m][q][2], d[m][q][3]);
            if (bias){
                float b0 = bias[col], b1 = bias[col+1];
                v0.x += b0; v0.y += b1; v1.x += b0; v1.y += b1;
            }
            *(float2*)(C + (size_t)row0*ldc + col) = v0;
            *(float2*)(C + (size_t)(row0+8)*ldc + col) = v1;
        }
}

// ---------------- persistent LSTM scan (batch-split) ----------------
// 2 batch groups x 64 column-CTAs. CTA (grp,c): batch rows grp*32..+31,
// hidden units c*16..+15 (64 gate cols). Wh slice (1-term fp16) smem-resident.
// Per step: gates = h @ WhS^T (M=32,N=64,K=1024), fused cell update (c in regs),
// gx prefetched via cp.async, then per-group 64-CTA barrier.
#define S_WH   0                 // 64 rows x 2064B = 132096
#define S_A0   132096            // 32 x 528 = 16896
#define S_A1   148992            // 16896
#define S_GX   165888            // 32 x 272 = 8704 (fp32, 68 floats/row)
#define S_GT   174592            // 32 x 272 = 8704 (fp32, 68 floats/row)
#define S_TOT  183296

__global__ __launch_bounds__(256) void lstm_scan(const float* __restrict__ bh){
    extern __shared__ char sm[];
    const int tid = threadIdx.x, wid = tid >> 5, l = tid & 31;
    const int cta = blockIdx.x;
    const int grp = cta >> 6;          // batch group 0/1
    const int c   = cta & 63;          // column slice

    // resident Wh slice: rows c*64 .. c*64+63, stride 2064B
    const half_t* WB = g_WhS_hi + (size_t)(c * 64) * HID;
#pragma unroll
    for (int j = 0; j < 32; j++){
        int u = tid + j * 256;
        int row = u >> 7, q = u & 127;
        *(uint4*)(sm + S_WH + row*2064 + q*16) = *((const uint4*)(WB + (size_t)row*HID) + q);
    }

    const int wm0 = (wid & 1) * 16, wn0 = (wid >> 1) * 16;
    uint32_t sbase = smem_u32(sm);
    uint32_t aA0 = sbase + S_A0 + (uint32_t)(wm0 + (l & 15)) * 528 + (l >> 4) * 16;
    uint32_t aA1 = aA0 + (S_A1 - S_A0);
    const int grp8 = l >> 3;
    const int n_off = (grp8 >> 1) * 8 + (l & 7);
    const int kblk = grp8 & 1;
    uint32_t aB = sbase + S_WH + (uint32_t)(wn0 + n_off) * 2064 + kblk * 16;
    float* Gt  = (float*)(sm + S_GT);
    float* Sgx = (float*)(sm + S_GX);

    // hoisted epilogue constants; cell state in registers
    int ep_b[2], ep_jj[2]; float bhv[2][4]; float creg[2] = {0.f, 0.f};
#pragma unroll
    for (int e = 0; e < 2; e++){
        int p = tid + e * 256;
        ep_b[e] = p >> 4; ep_jj[e] = p & 15;
        int jb = c * 16 + ep_jj[e];
#pragma unroll
        for (int g = 0; g < 4; g++) bhv[e][g] = bh[g * HID + jb];
    }
    unsigned int* cnt = &g_cnt2[grp * 32];
    __syncthreads();

    for (int s = 0; s < SQ; s++){
        const int sel = s & 1;
        const half_t* hh = g_h[sel]     + (size_t)grp * 32 * HID;
        half_t*      nhh = g_h[sel ^ 1] + (size_t)grp * 32 * HID;

        // prefetch gx tile (group committed first)
        const float* gxs = g_gx + (size_t)(s * NB + grp * 32) * G4;
#pragma unroll
        for (int e = 0; e < 2; e++){
            int idx = tid + e * 256;
            int b = idx >> 4, g = (idx >> 2) & 3, q = idx & 3;
            cp16(sbase + S_GX + b*272 + g*64 + q*16,
                 gxs + (size_t)b * G4 + g * HID + c * 16 + q * 4);
        }
        CP_COMMIT();

        // A-tile: 32 rows x 512B per chunk -> 1024 cp16 (4 iters x 256 thr)
        auto issueA = [&](int ch, int buf){
            const int k0 = ch * 256;
            uint32_t bb = sbase + (buf ? S_A1 : S_A0);
#pragma unroll
            for (int e = 0; e < 4; e++){
                int idx = tid + e * 256;
                int row = idx >> 5, q = idx & 31;
                cp16(bb + row*528 + q*16, hh + (size_t)row*HID + k0 + q*8);
            }
        };

        float d[2][4];
#pragma unroll
        for (int nn = 0; nn < 2; nn++)
#pragma unroll
            for (int e = 0; e < 4; e++) d[nn][e] = 0.f;

        issueA(0, 0); CP_COMMIT();
        for (int ch = 0; ch < 4; ch++){
            if (ch < 3){ issueA(ch + 1, (ch + 1) & 1); CP_COMMIT(); CP_WAIT(1); }
            else CP_WAIT(0);
            __syncthreads();
            uint32_t aA = (ch & 1) ? aA1 : aA0;
#pragma unroll
            for (int ks = 0; ks < 16; ks++){
                uint32_t ah[4], bb4[4];
                ldsm4(ah, aA + ks*32);
                ldsm4(bb4, aB + ch*512 + ks*32);
                mma_f16(d[0], ah, bb4);
                mma_f16(d[1], ah, bb4 + 2);
            }
            __syncthreads();
        }

        // stage gates: Gt[b][cc], cc = gate*16 + jj (68-float padded rows)
#pragma unroll
        for (int nn = 0; nn < 2; nn++){
            int r = wm0 + (l >> 2);
            int cc = wn0 + nn*8 + (l & 3)*2;
            Gt[r*68 + cc]       = d[nn][0];
            Gt[r*68 + cc + 1]   = d[nn][1];
            Gt[(r+8)*68 + cc]     = d[nn][2];
            Gt[(r+8)*68 + cc + 1] = d[nn][3];
        }
        __syncthreads();

        // fused cell update: 32 b x 16 jj pairs, 2 per thread; c state in regs
#pragma unroll
        for (int e = 0; e < 2; e++){
            int b = ep_b[e], jj = ep_jj[e];
            float gi = Gt[b*68 + jj]        + Sgx[b*68 + jj]        + bhv[e][0];
            float gf = Gt[b*68 + 16 + jj]   + Sgx[b*68 + 16 + jj]   + bhv[e][1];
            float gg = Gt[b*68 + 32 + jj]   + Sgx[b*68 + 32 + jj]   + bhv[e][2];
            float go = Gt[b*68 + 48 + jj]   + Sgx[b*68 + 48 + jj]   + bhv[e][3];
            gi = 1.f / (1.f + expf(-gi));
            gf = 1.f / (1.f + expf(-gf));
            gg = tanhf(gg);
            go = 1.f / (1.f + expf(-go));
            float cn = gf * creg[e] + gi * gg;
            creg[e] = cn;
            float hn = go * tanhf(cn);
            half_t h16 = __float2half_rn(hn);
            int j = c * 16 + jj;
            nhh[b*HID + j] = h16;
            g_hs[((size_t)(grp*32 + b) * SQ + s) * HID + j] = h16;
        }
        __syncthreads();

        // per-group barrier: release-atomic counter + single acquire-poller
        if (tid == 0){
            unsigned int dummy;
            asm volatile("atom.add.release.gpu.global.u32 %0, [%1], 1;"
                         : "=r"(dummy) : "l"(cnt) : "memory");
            unsigned int target = 64u * (unsigned int)(s + 1);
            unsigned int v;
            do {
                asm volatile("ld.acquire.gpu.global.u32 %0, [%1];"
                             : "=r"(v) : "l"(cnt) : "memory");
            } while (v < target);
        }
        __syncthreads();
    }
}

// ---------------------------------------------------------------------------
extern "C" void kernel_launch(void* const* d_in, const int* in_sizes, int n_in,
                              void* d_out, int out_size){
    const float* embed = (const float*)d_in[0];
    const float* Wi    = (const float*)d_in[1];
    const float* Wh    = (const float*)d_in[2];
    const float* bh    = (const float*)d_in[3];
    const float* Wo    = (const float*)d_in[4];
    const float* bo    = (const float*)d_in[5];
    const int*   x     = (const int*)d_in[6];
    float* out = (float*)d_out;

    const int TOT = NB * SQ;
    int logits_off = 0;
    if (out_size == TOT * (NA + 2)) logits_off = TOT;   // [dummy | logits | dummy]

    cudaFuncSetAttribute(gemm_mma,  cudaFuncAttributeMaxDynamicSharedMemorySize, GSM_TOT);
    cudaFuncSetAttribute(lstm_scan, cudaFuncAttributeMaxDynamicSharedMemorySize, S_TOT);

    float *gx_p;
    cudaGetSymbolAddress((void**)&gx_p, g_gx);
    half_t *xe, *wih, *wil, *woh, *wol, *hs, *whh, *whl;
    cudaGetSymbolAddress((void**)&xe,  g_xe);
    cudaGetSymbolAddress((void**)&wih, g_WiT_hi);
    cudaGetSymbolAddress((void**)&wil, g_WiT_lo);
    cudaGetSymbolAddress((void**)&woh, g_WoT_hi);
    cudaGetSymbolAddress((void**)&wol, g_WoT_lo);
    cudaGetSymbolAddress((void**)&hs,  g_hs);
    cudaGetSymbolAddress((void**)&whh, g_WhS_hi);
    cudaGetSymbolAddress((void**)&whl, g_WhS_lo);

    // 1) zero out + h0 + barrier counters
    init_zero<<<512, 256>>>(out, out_size);

    // 2a) Wi transpose + embedding gather (gx dependencies first, so gemm_gx
    //     lands at the ncu-profiled launch position)
    transpose_cvt<false><<<dim3(32, 128), dim3(32, 8)>>>(Wi, wih, wil, HID, G4);
    gather_xe<<<MTOT, 128>>>(embed, x);

    // 3) gx = xe @ WiT^T  [32768 x 4096]
    gemm_mma<<<dim3(G4/64, MTOT/128), 256, GSM_TOT>>>(xe, wih, wil, nullptr, gx_p, G4);

    // 2b) remaining weight prep
    transpose_cvt<true ><<<dim3(32, 128), dim3(32, 8)>>>(Wh, whh, whl, HID, G4);
    transpose_cvt<false><<<dim3(32, 4),   dim3(32, 8)>>>(Wo, woh, wol, HID, NA);

    // 4) persistent recurrent scan (2 groups x 64 CTAs)
    lstm_scan<<<128, 256, S_TOT>>>(bh);

    // 5) logits = hs @ WoT^T + bo  [32768 x 128]
    gemm_mma<<<dim3(NA/64, MTOT/128), 256, GSM_TOT>>>(hs, woh, wol, bo, out + logits_off, NA);
}

// round 7
// speedup vs baseline: 7.8064x; 1.2764x over previous
#include <cuda_runtime.h>
#include <cuda_fp16.h>
#include <math.h>
#include <stdint.h>

#define HID 1024
#define G4  4096
#define NB  64
#define SQ  512
#define NA  128
#define MTOT (NB*SQ)

typedef __half half_t;

// ---------------- device globals (allocation-free rule) ----------------
__device__ float g_gx[(size_t)SQ*NB*G4];                  // [S][B][4H] fp32
__device__ half_t g_xe[(size_t)MTOT*HID];                 // activations: single fp16
__device__ half_t g_WiT_hi[(size_t)G4*HID];               // weights: fp16 hi/lo
__device__ half_t g_WiT_lo[(size_t)G4*HID];
__device__ half_t g_WhS_hi[(size_t)G4*HID];               // scan-permuted rows (hi used)
__device__ half_t g_WhS_lo[(size_t)G4*HID];
__device__ half_t g_WoT_hi[(size_t)NA*HID];
__device__ half_t g_WoT_lo[(size_t)NA*HID];
__device__ half_t g_hs[(size_t)MTOT*HID];                 // [b*SQ+s][j]
__device__ half_t g_h[2][NB*HID];
__device__ unsigned int g_cnt2[64];                       // per-group barrier counters

// ---------------- helpers ----------------
static __device__ __forceinline__ uint32_t smem_u32(const void* p){
    uint32_t a;
    asm("{ .reg .u64 t; cvta.to.shared.u64 t, %1; cvt.u32.u64 %0, t; }" : "=r"(a) : "l"(p));
    return a;
}
static __device__ __forceinline__ void ldsm4(uint32_t* r, uint32_t a){
    asm volatile("ldmatrix.sync.aligned.m8n8.x4.shared.b16 {%0,%1,%2,%3}, [%4];"
        : "=r"(r[0]),"=r"(r[1]),"=r"(r[2]),"=r"(r[3]) : "r"(a));
}
static __device__ __forceinline__ void mma_f16(float* d, const uint32_t* a, const uint32_t* b){
    asm volatile("mma.sync.aligned.m16n8k16.row.col.f32.f16.f16.f32 "
        "{%0,%1,%2,%3}, {%4,%5,%6,%7}, {%8,%9}, {%0,%1,%2,%3};"
        : "+f"(d[0]),"+f"(d[1]),"+f"(d[2]),"+f"(d[3])
        : "r"(a[0]),"r"(a[1]),"r"(a[2]),"r"(a[3]), "r"(b[0]),"r"(b[1]));
}
static __device__ __forceinline__ void cp16(uint32_t dst, const void* src){
    asm volatile("cp.async.cg.shared.global [%0], [%1], 16;" :: "r"(dst), "l"(src));
}
#define CP_COMMIT() asm volatile("cp.async.commit_group;" ::: "memory")
#define CP_WAIT(n)  asm volatile("cp.async.wait_group %0;" :: "n"(n) : "memory")

static __device__ __forceinline__ void split_f16(float v, half_t& hi, half_t& lo){
    hi = __float2half_rn(v);
    lo = __float2half_rn(v - __half2float(hi));
}

// ---------------- prep kernels ----------------
__global__ void init_zero(float* out, int out_n){
    int i = blockIdx.x * blockDim.x + threadIdx.x;
    int stride = gridDim.x * blockDim.x;
    for (int p = i; p < out_n; p += stride) out[p] = 0.f;
    half_t z = __float2half(0.f);
    for (int p = i; p < NB*HID; p += stride){
        g_h[0][p] = z; g_h[1][p] = z;
    }
    if (i < 64) g_cnt2[i] = 0u;
}

// transpose W[K][N] -> T[n][k] split to fp16 hi/lo; PERM reorders Wh rows for the scan:
// CTA c owns units j=c*16..+15; slice row cc = gate*16 + (j&15); global row = c*64 + cc
template<bool PERM>
__global__ void transpose_cvt(const float* __restrict__ W,
                              half_t* __restrict__ Thi, half_t* __restrict__ Tlo,
                              int K, int N){
    __shared__ float tile[32][33];
    int k0 = blockIdx.x * 32, n0 = blockIdx.y * 32;
    int tx = threadIdx.x, ty = threadIdx.y;     // 32 x 8
    for (int i = ty; i < 32; i += 8)
        tile[i][tx] = W[(size_t)(k0 + i) * N + n0 + tx];
    __syncthreads();
    for (int i = ty; i < 32; i += 8){
        int n = n0 + i, k = k0 + tx;
        float v = tile[tx][i];
        int r = n;
        if (PERM) r = ((n & 1023) >> 4) * 64 + (n >> 10) * 16 + (n & 15);
        half_t hi, lo; split_f16(v, hi, lo);
        Thi[(size_t)r * K + k] = hi;
        Tlo[(size_t)r * K + k] = lo;
    }
}

__global__ void gather_xe(const float* __restrict__ embed, const int* __restrict__ x){
    int r = blockIdx.x;                 // 0..32767, r = s*64 + b
    int s = r >> 6, b = r & 63;
    int tok = x[b * SQ + s];
    const float* src = embed + (size_t)tok * HID;
    for (int k = threadIdx.x; k < HID; k += blockDim.x)
        g_xe[(size_t)r * HID + k] = __float2half_rn(src[k]);
}

// ---------------- 1-term fp16 GEMM for gx: 128x128 tile ----------------
// C[M,N] tiles 128x128, K=1024. A[m][k], B[n][k] single fp16 -> C fp32.
// 8 warps 4x2, warp tile 32x64. Rows padded to 144B. cp.async double-buffered.
#define X_AO   0
#define X_BO   18432
#define XBUF   36864
#define XSM_TOT (2*XBUF)

__global__ __launch_bounds__(256) void gemm_gx1(
    const half_t* __restrict__ A, const half_t* __restrict__ B,
    float* __restrict__ C, int ldc)
{
    extern __shared__ char sm[];
    const int tid = threadIdx.x, wid = tid >> 5, l = tid & 31;
    const int n0 = blockIdx.x * 128, m0 = blockIdx.y * 128;
    const int wm0 = (wid & 3) * 32, wn0 = (wid >> 2) * 64;

    uint32_t sbase = smem_u32(sm);

    uint32_t aA = sbase + X_AO + (uint32_t)(wm0 + (l & 15)) * 144 + (l >> 4) * 16;
    const int grp8 = l >> 3;
    const int n_off = (grp8 >> 1) * 8 + (l & 7);
    const int kblk = grp8 & 1;
    uint32_t aB = sbase + X_BO + (uint32_t)(wn0 + n_off) * 144 + kblk * 16;

    float d[2][8][4];
#pragma unroll
    for (int m = 0; m < 2; m++)
#pragma unroll
        for (int q = 0; q < 8; q++)
#pragma unroll
            for (int e = 0; e < 4; e++) d[m][q][e] = 0.f;

    auto issue = [&](int c, int buf){
        const int k0 = c * 64;
        uint32_t bb = sbase + buf * XBUF;
#pragma unroll
        for (int e = 0; e < 4; e++){
            int idx = tid + e * 256;
            int row = idx >> 3, q = idx & 7;
            cp16(bb + X_AO + row*144 + q*16, A + (size_t)(m0 + row)*HID + k0 + q*8);
            cp16(bb + X_BO + row*144 + q*16, B + (size_t)(n0 + row)*HID + k0 + q*8);
        }
    };

    issue(0, 0); CP_COMMIT();

    for (int c = 0; c < 16; c++){
        if (c < 15){ issue(c + 1, (c + 1) & 1); CP_COMMIT(); CP_WAIT(1); }
        else CP_WAIT(0);
        __syncthreads();
        const uint32_t bo = (uint32_t)(c & 1) * XBUF;
#pragma unroll
        for (int ks = 0; ks < 4; ks++){
            uint32_t ah[2][4];
            ldsm4(ah[0], aA + bo + ks*32);
            ldsm4(ah[1], aA + bo + 16*144 + ks*32);
            uint32_t bb4[4][4];
#pragma unroll
            for (int g = 0; g < 4; g++)
                ldsm4(bb4[g], aB + bo + g*2304 + ks*32);
#pragma unroll
            for (int m = 0; m < 2; m++)
#pragma unroll
                for (int g = 0; g < 4; g++)
#pragma unroll
                    for (int nn = 0; nn < 2; nn++)
                        mma_f16(d[m][g*2+nn], ah[m], bb4[g] + nn*2);
        }
        __syncthreads();
    }

#pragma unroll
    for (int m = 0; m < 2; m++)
#pragma unroll
        for (int q = 0; q < 8; q++){
            int row0 = m0 + wm0 + m*16 + (l >> 2);
            int col  = n0 + wn0 + q*8 + (l & 3)*2;
            *(float2*)(C + (size_t)row0*ldc + col)     = make_float2(d[m][q][0], d[m][q][1]);
            *(float2*)(C + (size_t)(row0+8)*ldc + col) = make_float2(d[m][q][2], d[m][q][3]);
        }
}

// ---------------- fp16x2 warp-MMA GEMM (logits) ----------------
#define GBUF   36864            // per buffer: A 18432 | Bh 9216 | Bl 9216
#define G_AO   0
#define G_BHO  18432
#define G_BLO  27648
#define GSM_TOT (2*GBUF)

__global__ __launch_bounds__(256) void gemm_mma(
    const half_t* __restrict__ A,
    const half_t* __restrict__ Bhi, const half_t* __restrict__ Blo,
    const float* __restrict__ bias, float* __restrict__ C, int ldc)
{
    extern __shared__ char sm[];
    const int tid = threadIdx.x, wid = tid >> 5, l = tid & 31;
    const int n0 = blockIdx.x * 64, m0 = blockIdx.y * 128;
    const int wm0 = (wid & 3) * 32, wn0 = (wid >> 2) * 32;

    uint32_t sbase = smem_u32(sm);

    const int a_row = tid >> 1, a_q = tid & 1;
    const int b_row = tid >> 2, b_q = tid & 3;

    uint32_t aA = sbase + G_AO + (uint32_t)(wm0 + (l & 15)) * 144 + (l >> 4) * 16;
    const int grp = l >> 3;
    const int n_off = (grp >> 1) * 8 + (l & 7);
    const int kblk = grp & 1;
    uint32_t aBh = sbase + G_BHO + (uint32_t)(wn0 + n_off) * 144 + kblk * 16;
    uint32_t aBl = sbase + G_BLO + (uint32_t)(wn0 + n_off) * 144 + kblk * 16;

    float d[2][4][4];
#pragma unroll
    for (int m = 0; m < 2; m++)
#pragma unroll
        for (int q = 0; q < 4; q++)
#pragma unroll
            for (int e = 0; e < 4; e++) d[m][q][e] = 0.f;

    auto issue = [&](int c, int buf){
        const int k0 = c * 64;
        uint32_t bb = sbase + buf * GBUF;
#pragma unroll
        for (int j = 0; j < 4; j++){
            int q = a_q + j * 2;
            cp16(bb + G_AO + a_row*144 + q*16, A + (size_t)(m0 + a_row)*HID + k0 + q*8);
        }
#pragma unroll
        for (int j = 0; j < 2; j++){
            int q = b_q + j * 4;
            cp16(bb + G_BHO + b_row*144 + q*16, Bhi + (size_t)(n0 + b_row)*HID + k0 + q*8);
            cp16(bb + G_BLO + b_row*144 + q*16, Blo + (size_t)(n0 + b_row)*HID + k0 + q*8);
        }
    };

    issue(0, 0); CP_COMMIT();

    for (int c = 0; c < 16; c++){
        if (c < 15){ issue(c + 1, (c + 1) & 1); CP_COMMIT(); CP_WAIT(1); }
        else CP_WAIT(0);
        __syncthreads();
        const uint32_t bo = (uint32_t)(c & 1) * GBUF;
#pragma unroll
        for (int ks = 0; ks < 4; ks++){
            uint32_t ah[2][4];
            ldsm4(ah[0], aA + bo + ks*32);
            ldsm4(ah[1], aA + bo + 16*144 + ks*32);
#pragma unroll
            for (int g = 0; g < 2; g++){
                uint32_t bh4[4], bl4[4];
                ldsm4(bh4, aBh + bo + g*2304 + ks*32);
                ldsm4(bl4, aBl + bo + g*2304 + ks*32);
#pragma unroll
                for (int m = 0; m < 2; m++)
#pragma unroll
                    for (int nn = 0; nn < 2; nn++){
                        float* dd = d[m][g*2+nn];
                        mma_f16(dd, ah[m], bh4 + nn*2);
                        mma_f16(dd, ah[m], bl4 + nn*2);
                    }
            }
        }
        __syncthreads();
    }

#pragma unroll
    for (int m = 0; m < 2; m++)
#pragma unroll
        for (int q = 0; q < 4; q++){
            int row0 = m0 + wm0 + m*16 + (l >> 2);
            int col  = n0 + wn0 + q*8 + (l & 3)*2;
            float2 v0 = make_float2(d[m][q][0], d[m][q][1]);
            float2 v1 = make_float2(d[m][q][2], d[m][q][3]);
            if (bias){
                float b0 = bias[col], b1 = bias[col+1];
                v0.x += b0; v0.y += b1; v1.x += b0; v1.y += b1;
            }
            *(float2*)(C + (size_t)row0*ldc + col) = v0;
            *(float2*)(C + (size_t)(row0+8)*ldc + col) = v1;
        }
}

// ---------------- persistent LSTM scan (batch-split) ----------------
// 2 batch groups x 64 column-CTAs. CTA (grp,c): batch rows grp*32..+31,
// hidden units c*16..+15 (64 gate cols). Wh slice (1-term fp16) smem-resident.
#define S_WH   0                 // 64 rows x 2064B = 132096
#define S_A0   132096            // 32 x 528 = 16896
#define S_A1   148992            // 16896
#define S_GX   165888            // 32 x 272 = 8704 (fp32, 68 floats/row)
#define S_GT   174592            // 32 x 272 = 8704 (fp32, 68 floats/row)
#define S_TOT  183296

__global__ __launch_bounds__(256) void lstm_scan(const float* __restrict__ bh){
    extern __shared__ char sm[];
    const int tid = threadIdx.x, wid = tid >> 5, l = tid & 31;
    const int cta = blockIdx.x;
    const int grp = cta >> 6;          // batch group 0/1
    const int c   = cta & 63;          // column slice

    // resident Wh slice: rows c*64 .. c*64+63, stride 2064B
    const half_t* WB = g_WhS_hi + (size_t)(c * 64) * HID;
#pragma unroll
    for (int j = 0; j < 32; j++){
        int u = tid + j * 256;
        int row = u >> 7, q = u & 127;
        *(uint4*)(sm + S_WH + row*2064 + q*16) = *((const uint4*)(WB + (size_t)row*HID) + q);
    }

    const int wm0 = (wid & 1) * 16, wn0 = (wid >> 1) * 16;
    uint32_t sbase = smem_u32(sm);
    uint32_t aA0 = sbase + S_A0 + (uint32_t)(wm0 + (l & 15)) * 528 + (l >> 4) * 16;
    uint32_t aA1 = aA0 + (S_A1 - S_A0);
    const int grp8 = l >> 3;
    const int n_off = (grp8 >> 1) * 8 + (l & 7);
    const int kblk = grp8 & 1;
    uint32_t aB = sbase + S_WH + (uint32_t)(wn0 + n_off) * 2064 + kblk * 16;
    float* Gt  = (float*)(sm + S_GT);
    float* Sgx = (float*)(sm + S_GX);

    // hoisted epilogue constants; cell state in registers
    int ep_b[2], ep_jj[2]; float bhv[2][4]; float creg[2] = {0.f, 0.f};
#pragma unroll
    for (int e = 0; e < 2; e++){
        int p = tid + e * 256;
        ep_b[e] = p >> 4; ep_jj[e] = p & 15;
        int jb = c * 16 + ep_jj[e];
#pragma unroll
        for (int g = 0; g < 4; g++) bhv[e][g] = bh[g * HID + jb];
    }
    unsigned int* cnt = &g_cnt2[grp * 32];
    __syncthreads();

    for (int s = 0; s < SQ; s++){
        const int sel = s & 1;
        const half_t* hh = g_h[sel]     + (size_t)grp * 32 * HID;
        half_t*      nhh = g_h[sel ^ 1] + (size_t)grp * 32 * HID;

        // prefetch gx tile
        const float* gxs = g_gx + (size_t)(s * NB + grp * 32) * G4;
#pragma unroll
        for (int e = 0; e < 2; e++){
            int idx = tid + e * 256;
            int b = idx >> 4, g = (idx >> 2) & 3, q = idx & 3;
            cp16(sbase + S_GX + b*272 + g*64 + q*16,
                 gxs + (size_t)b * G4 + g * HID + c * 16 + q * 4);
        }
        CP_COMMIT();

        // A-tile: 32 rows x 512B per chunk -> 1024 cp16 (4 iters x 256 thr)
        auto issueA = [&](int ch, int buf){
            const int k0 = ch * 256;
            uint32_t bb = sbase + (buf ? S_A1 : S_A0);
#pragma unroll
            for (int e = 0; e < 4; e++){
                int idx = tid + e * 256;
                int row = idx >> 5, q = idx & 31;
                cp16(bb + row*528 + q*16, hh + (size_t)row*HID + k0 + q*8);
            }
        };

        float d[2][4];
#pragma unroll
        for (int nn = 0; nn < 2; nn++)
#pragma unroll
            for (int e = 0; e < 4; e++) d[nn][e] = 0.f;

        issueA(0, 0); CP_COMMIT();
        for (int ch = 0; ch < 4; ch++){
            if (ch < 3){ issueA(ch + 1, (ch + 1) & 1); CP_COMMIT(); CP_WAIT(1); }
            else CP_WAIT(0);
            __syncthreads();
            uint32_t aA = (ch & 1) ? aA1 : aA0;
#pragma unroll
            for (int ks = 0; ks < 16; ks++){
                uint32_t ah[4], bb4[4];
                ldsm4(ah, aA + ks*32);
                ldsm4(bb4, aB + ch*512 + ks*32);
                mma_f16(d[0], ah, bb4);
                mma_f16(d[1], ah, bb4 + 2);
            }
            __syncthreads();
        }

        // stage gates: Gt[b][cc], cc = gate*16 + jj (68-float padded rows)
#pragma unroll
        for (int nn = 0; nn < 2; nn++){
            int r = wm0 + (l >> 2);
            int cc = wn0 + nn*8 + (l & 3)*2;
            Gt[r*68 + cc]       = d[nn][0];
            Gt[r*68 + cc + 1]   = d[nn][1];
            Gt[(r+8)*68 + cc]     = d[nn][2];
            Gt[(r+8)*68 + cc + 1] = d[nn][3];
        }
        __syncthreads();

        // fused cell update: 32 b x 16 jj pairs, 2 per thread; c state in regs
#pragma unroll
        for (int e = 0; e < 2; e++){
            int b = ep_b[e], jj = ep_jj[e];
            float gi = Gt[b*68 + jj]        + Sgx[b*68 + jj]        + bhv[e][0];
            float gf = Gt[b*68 + 16 + jj]   + Sgx[b*68 + 16 + jj]   + bhv[e][1];
            float gg = Gt[b*68 + 32 + jj]   + Sgx[b*68 + 32 + jj]   + bhv[e][2];
            float go = Gt[b*68 + 48 + jj]   + Sgx[b*68 + 48 + jj]   + bhv[e][3];
            gi = 1.f / (1.f + expf(-gi));
            gf = 1.f / (1.f + expf(-gf));
            gg = tanhf(gg);
            go = 1.f / (1.f + expf(-go));
            float cn = gf * creg[e] + gi * gg;
            creg[e] = cn;
            float hn = go * tanhf(cn);
            half_t h16 = __float2half_rn(hn);
            int j = c * 16 + jj;
            nhh[b*HID + j] = h16;
            g_hs[((size_t)(grp*32 + b) * SQ + s) * HID + j] = h16;
        }
        __syncthreads();

        // per-group barrier: release-atomic counter + single acquire-poller
        if (tid == 0){
            unsigned int dummy;
            asm volatile("atom.add.release.gpu.global.u32 %0, [%1], 1;"
                         : "=r"(dummy) : "l"(cnt) : "memory");
            unsigned int target = 64u * (unsigned int)(s + 1);
            unsigned int v;
            do {
                asm volatile("ld.acquire.gpu.global.u32 %0, [%1];"
                             : "=r"(v) : "l"(cnt) : "memory");
            } while (v < target);
        }
        __syncthreads();
    }
}

// ---------------------------------------------------------------------------
extern "C" void kernel_launch(void* const* d_in, const int* in_sizes, int n_in,
                              void* d_out, int out_size){
    const float* embed = (const float*)d_in[0];
    const float* Wi    = (const float*)d_in[1];
    const float* Wh    = (const float*)d_in[2];
    const float* bh    = (const float*)d_in[3];
    const float* Wo    = (const float*)d_in[4];
    const float* bo    = (const float*)d_in[5];
    const int*   x     = (const int*)d_in[6];
    float* out = (float*)d_out;

    const int TOT = NB * SQ;
    int logits_off = 0;
    if (out_size == TOT * (NA + 2)) logits_off = TOT;   // [dummy | logits | dummy]

    cudaFuncSetAttribute(gemm_gx1,  cudaFuncAttributeMaxDynamicSharedMemorySize, XSM_TOT);
    cudaFuncSetAttribute(gemm_mma,  cudaFuncAttributeMaxDynamicSharedMemorySize, GSM_TOT);
    cudaFuncSetAttribute(lstm_scan, cudaFuncAttributeMaxDynamicSharedMemorySize, S_TOT);

    float *gx_p;
    cudaGetSymbolAddress((void**)&gx_p, g_gx);
    half_t *xe, *wih, *wil, *woh, *wol, *hs, *whh, *whl;
    cudaGetSymbolAddress((void**)&xe,  g_xe);
    cudaGetSymbolAddress((void**)&wih, g_WiT_hi);
    cudaGetSymbolAddress((void**)&wil, g_WiT_lo);
    cudaGetSymbolAddress((void**)&woh, g_WoT_hi);
    cudaGetSymbolAddress((void**)&wol, g_WoT_lo);
    cudaGetSymbolAddress((void**)&hs,  g_hs);
    cudaGetSymbolAddress((void**)&whh, g_WhS_hi);
    cudaGetSymbolAddress((void**)&whl, g_WhS_lo);

    // 1) zero out + h0 + barrier counters
    init_zero<<<512, 256>>>(out, out_size);

    // 2a) Wi transpose + embedding gather (gx dependencies first)
    transpose_cvt<false><<<dim3(32, 128), dim3(32, 8)>>>(Wi, wih, wil, HID, G4);
    gather_xe<<<MTOT, 128>>>(embed, x);

    // 3) gx = xe @ WiT^T  [32768 x 4096], 1-term fp16, 128x128 tiles
    gemm_gx1<<<dim3(G4/128, MTOT/128), 256, XSM_TOT>>>(xe, wih, gx_p, G4);

    // 2b) remaining weight prep
    transpose_cvt<true ><<<dim3(32, 128), dim3(32, 8)>>>(Wh, whh, whl, HID, G4);
    transpose_cvt<false><<<dim3(32, 4),   dim3(32, 8)>>>(Wo, woh, wol, HID, NA);

    // 4) persistent recurrent scan (2 groups x 64 CTAs)
    lstm_scan<<<128, 256, S_TOT>>>(bh);

    // 5) logits = hs @ WoT^T + bo  [32768 x 128], 2-term
    gemm_mma<<<dim3(NA/64, MTOT/128), 256, GSM_TOT>>>(hs, woh, wol, bo, out + logits_off, NA);
}